// round 6
// baseline (speedup 1.0000x reference)
#include <cuda_runtime.h>
#include <cuda_bf16.h>
#include <math.h>

#define HS 65536
#define TT 128          // CTA tile: 64 cols tensor + 64 cols ffma
#define FTT 128         // head tile
#define TOUT 63489
#define NLAYER 20

__device__ float g_h[2][64 * HS];
__device__ float g_skip[64 * TOUT];
__device__ float g_w1t[NLAYER * 128 * 128];   // [l][k][m] fp32
__device__ float g_w2t[NLAYER * 64 * 128];    // [l][k][m]

// ---------------- common helpers ----------------
__device__ __forceinline__ unsigned pack_hl(float x){
    __nv_bfloat16 h=__float2bfloat16(x);
    __nv_bfloat16 l=__float2bfloat16(x-__bfloat162float(h));
    return (unsigned)__bfloat16_as_ushort(h) | ((unsigned)__bfloat16_as_ushort(l)<<16);
}
__device__ __forceinline__ int addrA(int m,int k,int kt){
    int ln=((m&7)<<2)|((k>>1)&3);
    int w=(k&1)|(((m>>3)&1)<<1)|(((k>>3)&1)<<2);
    return ((((m>>4)*kt+(k>>4))<<8)+(ln<<3)+w);
}
__device__ __forceinline__ int addrB64(int k,int t){   // B tile, 64 cols
    int ln=((t&7)<<2)|((k>>1)&3);
    int w=(k&1)|(((k>>3)&1)<<1);
    return ((((k>>4)*8+(t>>3))<<7)+(ln<<2)+w);
}
__device__ __forceinline__ int addrB128(int k,int t){  // B tile, 128 cols (head)
    int ln=((t&7)<<2)|((k>>1)&3);
    int w=(k&1)|(((k>>3)&1)<<1);
    return ((((k>>4)*16+(t>>3))<<7)+(ln<<2)+w);
}
__device__ __forceinline__ void mma_bf(float* d, const unsigned* a, const unsigned* b){
    asm volatile("mma.sync.aligned.m16n8k16.row.col.f32.bf16.bf16.f32 "
        "{%0,%1,%2,%3},{%4,%5,%6,%7},{%8,%9},{%0,%1,%2,%3};\n"
        :"+f"(d[0]),"+f"(d[1]),"+f"(d[2]),"+f"(d[3])
        :"r"(a[0]),"r"(a[1]),"r"(a[2]),"r"(a[3]),"r"(b[0]),"r"(b[1]));
}
__device__ __forceinline__ void loadA(const unsigned* s,int mt,int kc,int kt,int lane,unsigned* Ah,unsigned* Al){
    const uint4* p=(const uint4*)(s+(((mt*kt+kc)<<8)+(lane<<3)));
    uint4 q0=p[0],q1=p[1];
    Ah[0]=__byte_perm(q0.x,q0.y,0x5410); Al[0]=__byte_perm(q0.x,q0.y,0x7632);
    Ah[1]=__byte_perm(q0.z,q0.w,0x5410); Al[1]=__byte_perm(q0.z,q0.w,0x7632);
    Ah[2]=__byte_perm(q1.x,q1.y,0x5410); Al[2]=__byte_perm(q1.x,q1.y,0x7632);
    Ah[3]=__byte_perm(q1.z,q1.w,0x5410); Al[3]=__byte_perm(q1.z,q1.w,0x7632);
}
__device__ __forceinline__ void loadB64(const unsigned* s,int kc,int nt,int lane,unsigned* Bh,unsigned* Bl){
    uint4 q=*(const uint4*)(s+(((kc*8+nt)<<7)+(lane<<2)));
    Bh[0]=__byte_perm(q.x,q.y,0x5410); Bl[0]=__byte_perm(q.x,q.y,0x7632);
    Bh[1]=__byte_perm(q.z,q.w,0x5410); Bl[1]=__byte_perm(q.z,q.w,0x7632);
}
__device__ __forceinline__ void loadB128(const unsigned* s,int kc,int nt,int lane,unsigned* Bh,unsigned* Bl){
    uint4 q=*(const uint4*)(s+(((kc*16+nt)<<7)+(lane<<2)));
    Bh[0]=__byte_perm(q.x,q.y,0x5410); Bl[0]=__byte_perm(q.x,q.y,0x7632);
    Bh[1]=__byte_perm(q.z,q.w,0x5410); Bl[1]=__byte_perm(q.z,q.w,0x7632);
}
__device__ __forceinline__ float fast_tanh(float x){
    float e=__expf(-2.0f*fabsf(x)); return copysignf(__fdividef(1.0f-e,1.0f+e),x);
}
__device__ __forceinline__ float fast_sig(float x){ return __fdividef(1.0f,1.0f+__expf(-x)); }
#define BAR(id) asm volatile("bar.sync %0, 256;"::"r"(id):"memory")

// ---------------- init: h0, skip=0, transposed fp32 weights ----------------
__global__ void init_kernel(const float* __restrict__ in, const float* __restrict__ w0,
                            const float* __restrict__ b0,
                            const float* __restrict__ wf, const float* __restrict__ wg,
                            const float* __restrict__ wr, const float* __restrict__ ws){
    int st = gridDim.x*blockDim.x;
    int tid0 = blockIdx.x*blockDim.x+threadIdx.x;
    for (int i=tid0; i<64*HS; i+=st){
        int c=i>>16, t=i&(HS-1);
        g_h[0][i] = w0[c]*in[t] + b0[c];
    }
    for (int i=tid0; i<64*TOUT; i+=st) g_skip[i]=0.0f;
    for (int i=tid0; i<NLAYER*128*128; i+=st){
        int l=i>>14, r=i&16383, k=r>>7, m=r&127;
        int c=k&63, lr=k>>6;
        g_w1t[i] = (m<64)? wf[((l*64+m)*64+c)*2+lr] : wg[((l*64+(m-64))*64+c)*2+lr];
    }
    for (int i=tid0; i<NLAYER*64*128; i+=st){
        int l=i>>13, r=i&8191, k=r>>7, m=r&127;
        g_w2t[i] = (m<64)? wr[(l*64+m)*64+k] : ws[(l*64+(m-64))*64+k];
    }
}

// ---------------- hybrid layer kernel ----------------
// smem u32 units: sW1p[0,16384) sW2p[16384,24576) sXp/sF[24576,32768)
//                 sZp[32768,36864) fX/fF[36864,45056)   total 180224 B
#define SM_LAYER (45056*4)

__global__ void __launch_bounds__(512,1) layer_kernel(
    const float* __restrict__ wf, const float* __restrict__ wg,
    const float* __restrict__ wr, const float* __restrict__ ws,
    const float* __restrict__ bf, const float* __restrict__ bg,
    const float* __restrict__ br, const float* __restrict__ bs,
    const float* __restrict__ w1t, const float* __restrict__ w2t,
    int inbuf, int W, int d, int skip_shift)
{
    extern __shared__ unsigned smem[];
    unsigned* sW1p = smem;
    unsigned* sW2p = smem + 16384;
    unsigned* sXp  = smem + 24576;
    unsigned* sZp  = smem + 32768;
    float*    sF   = (float*)sXp;
    float*    fX   = (float*)(smem + 36864);

    const float* __restrict__ hin = g_h[inbuf];
    float* __restrict__ hout = g_h[1-inbuf];
    const int tid = threadIdx.x, lane = tid&31, warp = tid>>5;
    const int Wout = W - d;
    const int ntiles = (Wout + TT - 1) / TT;

    if (warp < 8){
        // stage packed tensor weights (256 threads)
        for (int idx=tid; idx<128*128; idx+=256){
            int k=idx>>7, m=idx&127;
            int c=k&63, lr=k>>6;
            float v = (m<64)? wf[(m*64+c)*2+lr] : wg[((m-64)*64+c)*2+lr];
            sW1p[addrA(m,k,8)] = pack_hl(v);
        }
        for (int idx=tid; idx<128*64; idx+=256){
            int k=idx>>7, m=idx&127;
            float v = (m<64)? wr[m*64+k] : ws[(m-64)*64+k];
            sW2p[addrA(m,k,4)] = pack_hl(v);
        }
    }
    __syncthreads();

    if (warp < 8){
        // =========== TENSOR PATH: cols [t0, t0+64) ===========
        const int wm = warp>>1, wn = warp&1;
        const int m0 = wm*32, n0 = wn*32;
        for (int tile=blockIdx.x; tile<ntiles; tile+=gridDim.x){
            const int t0 = tile*TT;
            for (int idx=tid; idx<128*64; idx+=256){
                int k=idx>>6, t=idx&63, c=k&63;
                int lt = t0+t;
                float v = (lt<Wout)? hin[c*HS + lt + ((k>=64)?d:0)] : 0.0f;
                sXp[addrB64(k,t)] = pack_hl(v);
            }
            BAR(2);

            float acc[2][4][4];
            #pragma unroll
            for (int a=0;a<2;a++)
                #pragma unroll
                for (int b=0;b<4;b++){acc[a][b][0]=acc[a][b][1]=acc[a][b][2]=acc[a][b][3]=0.f;}
            #pragma unroll
            for (int kc=0;kc<8;kc++){
                unsigned Ah[2][4],Al[2][4],Bh[4][2],Bl[4][2];
                loadA(sW1p,(m0>>4),kc,8,lane,Ah[0],Al[0]);
                loadA(sW1p,(m0>>4)+1,kc,8,lane,Ah[1],Al[1]);
                #pragma unroll
                for (int nt=0;nt<4;nt++) loadB64(sXp,kc,(n0>>3)+nt,lane,Bh[nt],Bl[nt]);
                #pragma unroll
                for (int mt=0;mt<2;mt++)
                    #pragma unroll
                    for (int nt=0;nt<4;nt++){
                        mma_bf(acc[mt][nt],Ah[mt],Bh[nt]);
                        mma_bf(acc[mt][nt],Ah[mt],Bl[nt]);
                        mma_bf(acc[mt][nt],Al[mt],Bh[nt]);
                    }
            }
            BAR(2);
            #pragma unroll
            for (int mt=0;mt<2;mt++){
                int mbase = m0+mt*16+(lane>>2);
                #pragma unroll
                for (int nt=0;nt<4;nt++){
                    int tb = n0+nt*8+((lane&3)<<1);
                    #pragma unroll
                    for (int r=0;r<4;r++){
                        int m = mbase + ((r&2)?8:0);
                        int t = tb + (r&1);
                        float v = acc[mt][nt][r];
                        v = (m<64)? fast_tanh(v+bf[m]) : fast_sig(v+bg[m-64]);
                        sF[m*64+t] = v;
                    }
                }
            }
            BAR(2);
            for (int idx=tid; idx<64*64; idx+=256){
                int c=idx>>6, t=idx&63;
                sZp[addrB64(c,t)] = pack_hl(sF[c*64+t]*sF[(c+64)*64+t]);
            }
            BAR(2);

            float ac2[2][4][4];
            #pragma unroll
            for (int a=0;a<2;a++)
                #pragma unroll
                for (int b=0;b<4;b++){ac2[a][b][0]=ac2[a][b][1]=ac2[a][b][2]=ac2[a][b][3]=0.f;}
            #pragma unroll
            for (int kc=0;kc<4;kc++){
                unsigned Ah[2][4],Al[2][4],Bh[4][2],Bl[4][2];
                loadA(sW2p,(m0>>4),kc,4,lane,Ah[0],Al[0]);
                loadA(sW2p,(m0>>4)+1,kc,4,lane,Ah[1],Al[1]);
                #pragma unroll
                for (int nt=0;nt<4;nt++) loadB64(sZp,kc,(n0>>3)+nt,lane,Bh[nt],Bl[nt]);
                #pragma unroll
                for (int mt=0;mt<2;mt++)
                    #pragma unroll
                    for (int nt=0;nt<4;nt++){
                        mma_bf(ac2[mt][nt],Ah[mt],Bh[nt]);
                        mma_bf(ac2[mt][nt],Ah[mt],Bl[nt]);
                        mma_bf(ac2[mt][nt],Al[mt],Bh[nt]);
                    }
            }
            #pragma unroll
            for (int mt=0;mt<2;mt++){
                int mbase = m0+mt*16+(lane>>2);
                #pragma unroll
                for (int nt=0;nt<4;nt++){
                    int tb = n0+nt*8+((lane&3)<<1);
                    #pragma unroll
                    for (int r=0;r<4;r++){
                        int m = mbase + ((r&2)?8:0);
                        int gt = t0 + tb + (r&1);
                        float v = ac2[mt][nt][r];
                        if (m<64){
                            if (gt<Wout) hout[m*HS+gt] = v + br[m] + hin[m*HS+gt+d];
                        } else {
                            int gc = gt - skip_shift;
                            if (gt<Wout && gc>=0 && gc<TOUT)
                                g_skip[(m-64)*TOUT+gc] += v + bs[m-64];
                        }
                    }
                }
            }
            BAR(2);
        }
    } else {
        // =========== FFMA PATH: cols [t0+64, t0+128) ===========
        const int ftid = tid - 256;
        const int tg = ftid & 15, mg = ftid >> 4;
        const int tb = tg*4, mb = mg*8;
        for (int tile=blockIdx.x; tile<ntiles; tile+=gridDim.x){
            const int t0 = tile*TT + 64;
            for (int idx=ftid; idx<128*64; idx+=256){
                int k=idx>>6, t=idx&63, c=k&63;
                int lt = t0+t;
                fX[k*64+t] = (lt<Wout)? hin[c*HS + lt + ((k>=64)?d:0)] : 0.0f;
            }
            BAR(1);

            float acc[8][4];
            #pragma unroll
            for (int i=0;i<8;i++){acc[i][0]=acc[i][1]=acc[i][2]=acc[i][3]=0.f;}
            #pragma unroll 8
            for (int k=0;k<128;k++){
                float a[8], b[4];
                *(float4*)&a[0] = *(const float4*)(w1t + k*128 + mb);
                *(float4*)&a[4] = *(const float4*)(w1t + k*128 + mb + 4);
                *(float4*)&b[0] = *(const float4*)&fX[k*64 + tb];
                #pragma unroll
                for (int i=0;i<8;i++)
                    #pragma unroll
                    for (int j=0;j<4;j++) acc[i][j] += a[i]*b[j];
            }
            BAR(1);
            #pragma unroll
            for (int i=0;i<8;i++){
                int m = mb+i;
                float bias = (m<64)? bf[m] : bg[m-64];
                #pragma unroll
                for (int j=0;j<4;j++){
                    float v = acc[i][j] + bias;
                    v = (m<64)? fast_tanh(v) : fast_sig(v);
                    fX[m*64 + tb + j] = v;
                }
            }
            BAR(1);
            for (int idx=ftid; idx<64*64; idx+=256)
                fX[idx] = fX[idx]*fX[4096+idx];
            BAR(1);

            float ac2[8][4];
            #pragma unroll
            for (int i=0;i<8;i++){ac2[i][0]=ac2[i][1]=ac2[i][2]=ac2[i][3]=0.f;}
            #pragma unroll 8
            for (int k=0;k<64;k++){
                float a[8], b[4];
                *(float4*)&a[0] = *(const float4*)(w2t + k*128 + mb);
                *(float4*)&a[4] = *(const float4*)(w2t + k*128 + mb + 4);
                *(float4*)&b[0] = *(const float4*)&fX[k*64 + tb];
                #pragma unroll
                for (int i=0;i<8;i++)
                    #pragma unroll
                    for (int j=0;j<4;j++) ac2[i][j] += a[i]*b[j];
            }
            if (mb < 64){
                #pragma unroll
                for (int i=0;i<8;i++){
                    int m = mb+i;
                    float bias = br[m];
                    #pragma unroll
                    for (int j=0;j<4;j++){
                        int gt = t0 + tb + j;
                        if (gt<Wout) hout[m*HS+gt] = ac2[i][j] + bias + hin[m*HS+gt+d];
                    }
                }
            } else {
                #pragma unroll
                for (int i=0;i<8;i++){
                    int s = mb-64+i;
                    float bias = bs[s];
                    #pragma unroll
                    for (int j=0;j<4;j++){
                        int gt = t0 + tb + j;
                        int gc = gt - skip_shift;
                        if (gt<Wout && gc>=0 && gc<TOUT)
                            g_skip[s*TOUT+gc] += ac2[i][j] + bias;
                    }
                }
            }
            BAR(1);
        }
    }
}

// ---------------- output head (R2 machinery) ----------------
#define SM_FINAL (36864*4)
__global__ void __launch_bounds__(512,1) final_kernel(
    const float* __restrict__ alpha,
    const float* __restrict__ w0p, const float* __restrict__ b0p,
    const float* __restrict__ w1p, const float* __restrict__ b1p,
    float* __restrict__ out)
{
    extern __shared__ unsigned fs[];
    unsigned* sW0=fs; unsigned* sW1=fs+4096; unsigned* sB0=fs+20480; unsigned* sB1=fs+28672;
    const int tid=threadIdx.x, lane=tid&31, wrp=tid>>5;
    const int wm=wrp>>2, n0=(wrp&3)*32;

    for (int i=tid;i<64*64;i+=512) sW0[addrA(i>>6,i&63,4)]=pack_hl(w0p[i]);
    for (int i=tid;i<256*64;i+=512) sW1[addrA(i>>6,i&63,4)]=pack_hl(w1p[i]);
    __syncthreads();

    const int nt_total=(TOUT+FTT-1)/FTT;
    for (int tile=blockIdx.x; tile<nt_total; tile+=gridDim.x){
        const int t0=tile*FTT;
        for (int i=tid;i<64*FTT;i+=512){
            int c=i>>7, t=i&(FTT-1), gt=t0+t;
            float v=(gt<TOUT)?g_skip[c*TOUT+gt]:0.0f;
            v=(v>0.f)?v:alpha[c]*v;
            sB0[addrB128(c,t)]=pack_hl(v);
        }
        __syncthreads();

        float a0[4][4];
        #pragma unroll
        for (int b=0;b<4;b++){a0[b][0]=a0[b][1]=a0[b][2]=a0[b][3]=0.f;}
        #pragma unroll
        for (int kc=0;kc<4;kc++){
            unsigned Ah[4],Al[4],Bh[4][2],Bl[4][2];
            loadA(sW0,wm,kc,4,lane,Ah,Al);
            #pragma unroll
            for (int nt=0;nt<4;nt++) loadB128(sB0,kc,(n0>>3)+nt,lane,Bh[nt],Bl[nt]);
            #pragma unroll
            for (int nt=0;nt<4;nt++){
                mma_bf(a0[nt],Ah,Bh[nt]); mma_bf(a0[nt],Ah,Bl[nt]); mma_bf(a0[nt],Al,Bh[nt]);
            }
        }
        #pragma unroll
        for (int nt=0;nt<4;nt++){
            int tb=n0+nt*8+((lane&3)<<1);
            #pragma unroll
            for (int r=0;r<4;r++){
                int m=wm*16+(lane>>2)+((r&2)?8:0);
                float v=a0[nt][r]+b0p[m];
                v=(v>0.f)?v:alpha[64+m]*v;
                sB1[addrB128(m,tb+(r&1))]=pack_hl(v);
            }
        }
        __syncthreads();

        float a1[4][4][4];
        #pragma unroll
        for (int a=0;a<4;a++)
            #pragma unroll
            for (int b=0;b<4;b++){a1[a][b][0]=a1[a][b][1]=a1[a][b][2]=a1[a][b][3]=0.f;}
        #pragma unroll
        for (int kc=0;kc<4;kc++){
            unsigned Ah[4][4],Al[4][4],Bh[4][2],Bl[4][2];
            #pragma unroll
            for (int mt=0;mt<4;mt++) loadA(sW1,wm*4+mt,kc,4,lane,Ah[mt],Al[mt]);
            #pragma unroll
            for (int nt=0;nt<4;nt++) loadB128(sB1,kc,(n0>>3)+nt,lane,Bh[nt],Bl[nt]);
            #pragma unroll
            for (int mt=0;mt<4;mt++)
                #pragma unroll
                for (int nt=0;nt<4;nt++){
                    mma_bf(a1[mt][nt],Ah[mt],Bh[nt]); mma_bf(a1[mt][nt],Ah[mt],Bl[nt]); mma_bf(a1[mt][nt],Al[mt],Bh[nt]);
                }
        }
        #pragma unroll
        for (int mt=0;mt<4;mt++){
            int mbq=wm*64+mt*16+(lane>>2);
            #pragma unroll
            for (int nt=0;nt<4;nt++){
                int tb=n0+nt*8+((lane&3)<<1);
                #pragma unroll
                for (int r=0;r<4;r++){
                    int m=mbq+((r&2)?8:0), gt=t0+tb+(r&1);
                    if (gt<TOUT) out[m*TOUT+gt]=a1[mt][nt][r]+b1p[m];
                }
            }
        }
        __syncthreads();
    }
}

// ---------------- launch ----------------
extern "C" void kernel_launch(void* const* d_in, const int* in_sizes, int n_in,
                              void* d_out, int out_size) {
    const float* input =(const float*)d_in[0];
    const float* w0    =(const float*)d_in[1];
    const float* b0    =(const float*)d_in[2];
    const float* wf    =(const float*)d_in[3];
    const float* bf    =(const float*)d_in[4];
    const float* wg    =(const float*)d_in[5];
    const float* bg    =(const float*)d_in[6];
    const float* wr    =(const float*)d_in[7];
    const float* br    =(const float*)d_in[8];
    const float* ws    =(const float*)d_in[9];
    const float* bs    =(const float*)d_in[10];
    const float* alpha =(const float*)d_in[11];
    const float* w_out0=(const float*)d_in[12];
    const float* b_out0=(const float*)d_in[13];
    const float* w_out1=(const float*)d_in[14];
    const float* b_out1=(const float*)d_in[15];

    cudaFuncSetAttribute(layer_kernel, cudaFuncAttributeMaxDynamicSharedMemorySize, SM_LAYER);
    cudaFuncSetAttribute(final_kernel, cudaFuncAttributeMaxDynamicSharedMemorySize, SM_FINAL);

    init_kernel<<<512,256>>>(input, w0, b0, wf, wg, wr, ws);

    float* w1t_base = nullptr; float* w2t_base = nullptr;
    cudaGetSymbolAddress((void**)&w1t_base, g_w1t);
    cudaGetSymbolAddress((void**)&w2t_base, g_w2t);

    int W = HS, offset = 2048, buf = 0;
    for (int i = 0; i < NLAYER; i++){
        int d = 1 << (i % 10);
        offset -= d;
        layer_kernel<<<148,512,SM_LAYER>>>(
            wf + i*64*64*2, wg + i*64*64*2, wr + i*64*64, ws + i*64*64,
            bf + i*64, bg + i*64, br + i*64, bs + i*64,
            w1t_base + i*128*128, w2t_base + i*64*128,
            buf, W, d, offset - 1);
        W -= d; buf ^= 1;
    }
    final_kernel<<<148,512,SM_FINAL>>>(alpha, w_out0, b_out0, w_out1, b_out1, (float*)d_out);
}

// round 7
// speedup vs baseline: 1.0608x; 1.0608x over previous
#include <cuda_runtime.h>
#include <cuda_bf16.h>
#include <math.h>

#define HS 65536
#define TT 128
#define FTT 128
#define TOUT 63489
#define NLAYER 20

__device__ float g_h[2][64 * HS];
__device__ float g_skip[64 * TOUT];
__device__ float g_w1t[NLAYER * 128 * 128];   // [l][k][m] fp32
__device__ float g_w2t[NLAYER * 64 * 128];

// ---------------- common helpers ----------------
__device__ __forceinline__ unsigned pack_hl(float x){
    __nv_bfloat16 h=__float2bfloat16(x);
    __nv_bfloat16 l=__float2bfloat16(x-__bfloat162float(h));
    return (unsigned)__bfloat16_as_ushort(h) | ((unsigned)__bfloat16_as_ushort(l)<<16);
}
__device__ __forceinline__ int addrA(int m,int k,int kt){
    int ln=((m&7)<<2)|((k>>1)&3);
    int w=(k&1)|(((m>>3)&1)<<1)|(((k>>3)&1)<<2);
    return ((((m>>4)*kt+(k>>4))<<8)+(ln<<3)+w);
}
__device__ __forceinline__ int addrB64(int k,int t){
    int ln=((t&7)<<2)|((k>>1)&3);
    int w=(k&1)|(((k>>3)&1)<<1);
    return ((((k>>4)*8+(t>>3))<<7)+(ln<<2)+w);
}
__device__ __forceinline__ int addrB128(int k,int t){
    int ln=((t&7)<<2)|((k>>1)&3);
    int w=(k&1)|(((k>>3)&1)<<1);
    return ((((k>>4)*16+(t>>3))<<7)+(ln<<2)+w);
}
__device__ __forceinline__ void mma_bf(float* d, const unsigned* a, const unsigned* b){
    asm volatile("mma.sync.aligned.m16n8k16.row.col.f32.bf16.bf16.f32 "
        "{%0,%1,%2,%3},{%4,%5,%6,%7},{%8,%9},{%0,%1,%2,%3};\n"
        :"+f"(d[0]),"+f"(d[1]),"+f"(d[2]),"+f"(d[3])
        :"r"(a[0]),"r"(a[1]),"r"(a[2]),"r"(a[3]),"r"(b[0]),"r"(b[1]));
}
__device__ __forceinline__ void loadA(const unsigned* s,int mt,int kc,int kt,int lane,unsigned* Ah,unsigned* Al){
    const uint4* p=(const uint4*)(s+(((mt*kt+kc)<<8)+(lane<<3)));
    uint4 q0=p[0],q1=p[1];
    Ah[0]=__byte_perm(q0.x,q0.y,0x5410); Al[0]=__byte_perm(q0.x,q0.y,0x7632);
    Ah[1]=__byte_perm(q0.z,q0.w,0x5410); Al[1]=__byte_perm(q0.z,q0.w,0x7632);
    Ah[2]=__byte_perm(q1.x,q1.y,0x5410); Al[2]=__byte_perm(q1.x,q1.y,0x7632);
    Ah[3]=__byte_perm(q1.z,q1.w,0x5410); Al[3]=__byte_perm(q1.z,q1.w,0x7632);
}
__device__ __forceinline__ void loadB64(const unsigned* s,int kc,int nt,int lane,unsigned* Bh,unsigned* Bl){
    uint4 q=*(const uint4*)(s+(((kc*8+nt)<<7)+(lane<<2)));
    Bh[0]=__byte_perm(q.x,q.y,0x5410); Bl[0]=__byte_perm(q.x,q.y,0x7632);
    Bh[1]=__byte_perm(q.z,q.w,0x5410); Bl[1]=__byte_perm(q.z,q.w,0x7632);
}
__device__ __forceinline__ void loadB128(const unsigned* s,int kc,int nt,int lane,unsigned* Bh,unsigned* Bl){
    uint4 q=*(const uint4*)(s+(((kc*16+nt)<<7)+(lane<<2)));
    Bh[0]=__byte_perm(q.x,q.y,0x5410); Bl[0]=__byte_perm(q.x,q.y,0x7632);
    Bh[1]=__byte_perm(q.z,q.w,0x5410); Bl[1]=__byte_perm(q.z,q.w,0x7632);
}
__device__ __forceinline__ float fast_tanh(float x){
    float e=__expf(-2.0f*fabsf(x)); return copysignf(__fdividef(1.0f-e,1.0f+e),x);
}
__device__ __forceinline__ float fast_sig(float x){ return __fdividef(1.0f,1.0f+__expf(-x)); }
#define BAR(id) asm volatile("bar.sync %0, 512;"::"r"(id):"memory")

// ---------------- init ----------------
__global__ void init_kernel(const float* __restrict__ in, const float* __restrict__ w0,
                            const float* __restrict__ b0,
                            const float* __restrict__ wf, const float* __restrict__ wg,
                            const float* __restrict__ wr, const float* __restrict__ ws){
    int st = gridDim.x*blockDim.x;
    int tid0 = blockIdx.x*blockDim.x+threadIdx.x;
    for (int i=tid0; i<64*HS; i+=st){
        int c=i>>16, t=i&(HS-1);
        g_h[0][i] = w0[c]*in[t] + b0[c];
    }
    for (int i=tid0; i<64*TOUT; i+=st) g_skip[i]=0.0f;
    for (int i=tid0; i<NLAYER*128*128; i+=st){
        int l=i>>14, r=i&16383, k=r>>7, m=r&127;
        int c=k&63, lr=k>>6;
        g_w1t[i] = (m<64)? wf[((l*64+m)*64+c)*2+lr] : wg[((l*64+(m-64))*64+c)*2+lr];
    }
    for (int i=tid0; i<NLAYER*64*128; i+=st){
        int l=i>>13, r=i&8191, k=r>>7, m=r&127;
        g_w2t[i] = (m<64)? wr[(l*64+m)*64+k] : ws[(l*64+(m-64))*64+k];
    }
}

// ---------------- hybrid layer kernel: 1024 threads, 16+16 warps ----------------
// u32 words: sW1p[0,16384) sW2p[16384,24576) sXp/sF[24576,32768) sZp[32768,36864)
//            fX[36864,45056)  = 180224 bytes
#define SM_LAYER (45056*4)

__global__ void __launch_bounds__(1024,1) layer_kernel(
    const float* __restrict__ wf, const float* __restrict__ wg,
    const float* __restrict__ wr, const float* __restrict__ ws,
    const float* __restrict__ bf, const float* __restrict__ bg,
    const float* __restrict__ br, const float* __restrict__ bs,
    const float* __restrict__ w1t, const float* __restrict__ w2t,
    int inbuf, int W, int d, int skip_shift)
{
    extern __shared__ unsigned smem[];
    unsigned* sW1p = smem;
    unsigned* sW2p = smem + 16384;
    unsigned* sXp  = smem + 24576;
    unsigned* sZp  = smem + 32768;
    float*    sF   = (float*)sXp;
    float*    fX   = (float*)(smem + 36864);

    const float* __restrict__ hin = g_h[inbuf];
    float* __restrict__ hout = g_h[1-inbuf];
    const int tid = threadIdx.x, lane = tid&31, warp = tid>>5;
    const int Wout = W - d;
    const int ntiles = (Wout + TT - 1) / TT;

    if (warp < 16){
        for (int idx=tid; idx<128*128; idx+=512){
            int k=idx>>7, m=idx&127;
            int c=k&63, lr=k>>6;
            float v = (m<64)? wf[(m*64+c)*2+lr] : wg[((m-64)*64+c)*2+lr];
            sW1p[addrA(m,k,8)] = pack_hl(v);
        }
        for (int idx=tid; idx<128*64; idx+=512){
            int k=idx>>7, m=idx&127;
            float v = (m<64)? wr[m*64+k] : ws[(m-64)*64+k];
            sW2p[addrA(m,k,4)] = pack_hl(v);
        }
    }
    __syncthreads();

    if (warp < 16){
        // ===== TENSOR PATH: cols [t0, t0+64), 16 warps =====
        const int wm = warp>>1;          // 8 m-tiles of 16
        const int n0 = (warp&1)*32;      // 2 n-groups of 32
        for (int tile=blockIdx.x; tile<ntiles; tile+=gridDim.x){
            const int t0 = tile*TT;
            for (int idx=tid; idx<128*64; idx+=512){
                int k=idx>>6, t=idx&63, c=k&63;
                int lt = t0+t;
                float v = (lt<Wout)? hin[c*HS + lt + ((k>=64)?d:0)] : 0.0f;
                sXp[addrB64(k,t)] = pack_hl(v);
            }
            BAR(2);

            float acc[4][4];
            #pragma unroll
            for (int b=0;b<4;b++){acc[b][0]=acc[b][1]=acc[b][2]=acc[b][3]=0.f;}
            #pragma unroll
            for (int kc=0;kc<8;kc++){
                unsigned Ah[4],Al[4],Bh[4][2],Bl[4][2];
                loadA(sW1p,wm,kc,8,lane,Ah,Al);
                #pragma unroll
                for (int nt=0;nt<4;nt++) loadB64(sXp,kc,(n0>>3)+nt,lane,Bh[nt],Bl[nt]);
                #pragma unroll
                for (int nt=0;nt<4;nt++){
                    mma_bf(acc[nt],Ah,Bh[nt]);
                    mma_bf(acc[nt],Ah,Bl[nt]);
                    mma_bf(acc[nt],Al,Bh[nt]);
                }
            }
            BAR(2);
            #pragma unroll
            for (int nt=0;nt<4;nt++){
                int tb = n0+nt*8+((lane&3)<<1);
                #pragma unroll
                for (int r=0;r<4;r++){
                    int m = wm*16 + (lane>>2) + ((r&2)?8:0);
                    int t = tb + (r&1);
                    float v = acc[nt][r];
                    v = (m<64)? fast_tanh(v+bf[m]) : fast_sig(v+bg[m-64]);
                    sF[m*64+t] = v;
                }
            }
            BAR(2);
            for (int idx=tid; idx<64*64; idx+=512){
                int c=idx>>6, t=idx&63;
                sZp[addrB64(c,t)] = pack_hl(sF[c*64+t]*sF[(c+64)*64+t]);
            }
            BAR(2);

            float ac2[4][4];
            #pragma unroll
            for (int b=0;b<4;b++){ac2[b][0]=ac2[b][1]=ac2[b][2]=ac2[b][3]=0.f;}
            #pragma unroll
            for (int kc=0;kc<4;kc++){
                unsigned Ah[4],Al[4],Bh[4][2],Bl[4][2];
                loadA(sW2p,wm,kc,4,lane,Ah,Al);
                #pragma unroll
                for (int nt=0;nt<4;nt++) loadB64(sZp,kc,(n0>>3)+nt,lane,Bh[nt],Bl[nt]);
                #pragma unroll
                for (int nt=0;nt<4;nt++){
                    mma_bf(ac2[nt],Ah,Bh[nt]);
                    mma_bf(ac2[nt],Ah,Bl[nt]);
                    mma_bf(ac2[nt],Al,Bh[nt]);
                }
            }
            #pragma unroll
            for (int nt=0;nt<4;nt++){
                int tb = n0+nt*8+((lane&3)<<1);
                #pragma unroll
                for (int r=0;r<4;r++){
                    int m = wm*16 + (lane>>2) + ((r&2)?8:0);
                    int gt = t0 + tb + (r&1);
                    float v = ac2[nt][r];
                    if (m<64){
                        if (gt<Wout) hout[m*HS+gt] = v + br[m] + hin[m*HS+gt+d];
                    } else {
                        int gc = gt - skip_shift;
                        if (gt<Wout && gc>=0 && gc<TOUT)
                            g_skip[(m-64)*TOUT+gc] += v + bs[m-64];
                    }
                }
            }
            BAR(2);
        }
    } else {
        // ===== FFMA PATH: cols [t0+64, t0+128), 16 warps =====
        const int ftid = tid - 512;
        const int tg = ftid & 15, mg = ftid >> 4;   // 16 t-groups x 4, 32 m-groups x 4
        const int tb = tg*4, mb = mg*4;
        for (int tile=blockIdx.x; tile<ntiles; tile+=gridDim.x){
            const int t0 = tile*TT + 64;
            for (int idx=ftid; idx<128*64; idx+=512){
                int k=idx>>6, t=idx&63, c=k&63;
                int lt = t0+t;
                fX[k*64+t] = (lt<Wout)? hin[c*HS + lt + ((k>=64)?d:0)] : 0.0f;
            }
            BAR(1);

            float acc[4][4];
            #pragma unroll
            for (int i=0;i<4;i++){acc[i][0]=acc[i][1]=acc[i][2]=acc[i][3]=0.f;}
            #pragma unroll 8
            for (int k=0;k<128;k++){
                float a[4], b[4];
                *(float4*)&a[0] = *(const float4*)(w1t + k*128 + mb);
                *(float4*)&b[0] = *(const float4*)&fX[k*64 + tb];
                #pragma unroll
                for (int i=0;i<4;i++)
                    #pragma unroll
                    for (int j=0;j<4;j++) acc[i][j] += a[i]*b[j];
            }
            BAR(1);
            #pragma unroll
            for (int i=0;i<4;i++){
                int m = mb+i;
                float bias = (m<64)? bf[m] : bg[m-64];
                #pragma unroll
                for (int j=0;j<4;j++){
                    float v = acc[i][j] + bias;
                    v = (m<64)? fast_tanh(v) : fast_sig(v);
                    fX[m*64 + tb + j] = v;
                }
            }
            BAR(1);
            for (int idx=ftid; idx<64*64; idx+=512)
                fX[idx] = fX[idx]*fX[4096+idx];
            BAR(1);

            float ac2[4][4];
            #pragma unroll
            for (int i=0;i<4;i++){ac2[i][0]=ac2[i][1]=ac2[i][2]=ac2[i][3]=0.f;}
            #pragma unroll 8
            for (int k=0;k<64;k++){
                float a[4], b[4];
                *(float4*)&a[0] = *(const float4*)(w2t + k*128 + mb);
                *(float4*)&b[0] = *(const float4*)&fX[k*64 + tb];
                #pragma unroll
                for (int i=0;i<4;i++)
                    #pragma unroll
                    for (int j=0;j<4;j++) ac2[i][j] += a[i]*b[j];
            }
            if (mb < 64){
                #pragma unroll
                for (int i=0;i<4;i++){
                    int m = mb+i;
                    float bias = br[m];
                    #pragma unroll
                    for (int j=0;j<4;j++){
                        int gt = t0 + tb + j;
                        if (gt<Wout) hout[m*HS+gt] = ac2[i][j] + bias + hin[m*HS+gt+d];
                    }
                }
            } else {
                #pragma unroll
                for (int i=0;i<4;i++){
                    int s = mb-64+i;
                    float bias = bs[s];
                    #pragma unroll
                    for (int j=0;j<4;j++){
                        int gt = t0 + tb + j;
                        int gc = gt - skip_shift;
                        if (gt<Wout && gc>=0 && gc<TOUT)
                            g_skip[s*TOUT+gc] += ac2[i][j] + bias;
                    }
                }
            }
            BAR(1);
        }
    }
}

// ---------------- output head ----------------
#define SM_FINAL (36864*4)
__global__ void __launch_bounds__(512,1) final_kernel(
    const float* __restrict__ alpha,
    const float* __restrict__ w0p, const float* __restrict__ b0p,
    const float* __restrict__ w1p, const float* __restrict__ b1p,
    float* __restrict__ out)
{
    extern __shared__ unsigned fs[];
    unsigned* sW0=fs; unsigned* sW1=fs+4096; unsigned* sB0=fs+20480; unsigned* sB1=fs+28672;
    const int tid=threadIdx.x, lane=tid&31, wrp=tid>>5;
    const int wm=wrp>>2, n0=(wrp&3)*32;

    for (int i=tid;i<64*64;i+=512) sW0[addrA(i>>6,i&63,4)]=pack_hl(w0p[i]);
    for (int i=tid;i<256*64;i+=512) sW1[addrA(i>>6,i&63,4)]=pack_hl(w1p[i]);
    __syncthreads();

    const int nt_total=(TOUT+FTT-1)/FTT;
    for (int tile=blockIdx.x; tile<nt_total; tile+=gridDim.x){
        const int t0=tile*FTT;
        for (int i=tid;i<64*FTT;i+=512){
            int c=i>>7, t=i&(FTT-1), gt=t0+t;
            float v=(gt<TOUT)?g_skip[c*TOUT+gt]:0.0f;
            v=(v>0.f)?v:alpha[c]*v;
            sB0[addrB128(c,t)]=pack_hl(v);
        }
        __syncthreads();

        float a0[4][4];
        #pragma unroll
        for (int b=0;b<4;b++){a0[b][0]=a0[b][1]=a0[b][2]=a0[b][3]=0.f;}
        #pragma unroll
        for (int kc=0;kc<4;kc++){
            unsigned Ah[4],Al[4],Bh[4][2],Bl[4][2];
            loadA(sW0,wm,kc,4,lane,Ah,Al);
            #pragma unroll
            for (int nt=0;nt<4;nt++) loadB128(sB0,kc,(n0>>3)+nt,lane,Bh[nt],Bl[nt]);
            #pragma unroll
            for (int nt=0;nt<4;nt++){
                mma_bf(a0[nt],Ah,Bh[nt]); mma_bf(a0[nt],Ah,Bl[nt]); mma_bf(a0[nt],Al,Bh[nt]);
            }
        }
        #pragma unroll
        for (int nt=0;nt<4;nt++){
            int tb=n0+nt*8+((lane&3)<<1);
            #pragma unroll
            for (int r=0;r<4;r++){
                int m=wm*16+(lane>>2)+((r&2)?8:0);
                float v=a0[nt][r]+b0p[m];
                v=(v>0.f)?v:alpha[64+m]*v;
                sB1[addrB128(m,tb+(r&1))]=pack_hl(v);
            }
        }
        __syncthreads();

        float a1[4][4][4];
        #pragma unroll
        for (int a=0;a<4;a++)
            #pragma unroll
            for (int b=0;b<4;b++){a1[a][b][0]=a1[a][b][1]=a1[a][b][2]=a1[a][b][3]=0.f;}
        #pragma unroll
        for (int kc=0;kc<4;kc++){
            unsigned Ah[4][4],Al[4][4],Bh[4][2],Bl[4][2];
            #pragma unroll
            for (int mt=0;mt<4;mt++) loadA(sW1,wm*4+mt,kc,4,lane,Ah[mt],Al[mt]);
            #pragma unroll
            for (int nt=0;nt<4;nt++) loadB128(sB1,kc,(n0>>3)+nt,lane,Bh[nt],Bl[nt]);
            #pragma unroll
            for (int mt=0;mt<4;mt++)
                #pragma unroll
                for (int nt=0;nt<4;nt++){
                    mma_bf(a1[mt][nt],Ah[mt],Bh[nt]); mma_bf(a1[mt][nt],Ah[mt],Bl[nt]); mma_bf(a1[mt][nt],Al[mt],Bh[nt]);
                }
        }
        #pragma unroll
        for (int mt=0;mt<4;mt++){
            int mbq=wm*64+mt*16+(lane>>2);
            #pragma unroll
            for (int nt=0;nt<4;nt++){
                int tb=n0+nt*8+((lane&3)<<1);
                #pragma unroll
                for (int r=0;r<4;r++){
                    int m=mbq+((r&2)?8:0), gt=t0+tb+(r&1);
                    if (gt<TOUT) out[m*TOUT+gt]=a1[mt][nt][r]+b1p[m];
                }
            }
        }
        __syncthreads();
    }
}

// ---------------- launch ----------------
extern "C" void kernel_launch(void* const* d_in, const int* in_sizes, int n_in,
                              void* d_out, int out_size) {
    const float* input =(const float*)d_in[0];
    const float* w0    =(const float*)d_in[1];
    const float* b0    =(const float*)d_in[2];
    const float* wf    =(const float*)d_in[3];
    const float* bf    =(const float*)d_in[4];
    const float* wg    =(const float*)d_in[5];
    const float* bg    =(const float*)d_in[6];
    const float* wr    =(const float*)d_in[7];
    const float* br    =(const float*)d_in[8];
    const float* ws    =(const float*)d_in[9];
    const float* bs    =(const float*)d_in[10];
    const float* alpha =(const float*)d_in[11];
    const float* w_out0=(const float*)d_in[12];
    const float* b_out0=(const float*)d_in[13];
    const float* w_out1=(const float*)d_in[14];
    const float* b_out1=(const float*)d_in[15];

    cudaFuncSetAttribute(layer_kernel, cudaFuncAttributeMaxDynamicSharedMemorySize, SM_LAYER);
    cudaFuncSetAttribute(final_kernel, cudaFuncAttributeMaxDynamicSharedMemorySize, SM_FINAL);

    init_kernel<<<512,256>>>(input, w0, b0, wf, wg, wr, ws);

    float* w1t_base = nullptr; float* w2t_base = nullptr;
    cudaGetSymbolAddress((void**)&w1t_base, g_w1t);
    cudaGetSymbolAddress((void**)&w2t_base, g_w2t);

    int W = HS, offset = 2048, buf = 0;
    for (int i = 0; i < NLAYER; i++){
        int d = 1 << (i % 10);
        offset -= d;
        layer_kernel<<<148,1024,SM_LAYER>>>(
            wf + i*64*64*2, wg + i*64*64*2, wr + i*64*64, ws + i*64*64,
            bf + i*64, bg + i*64, br + i*64, bs + i*64,
            w1t_base + i*128*128, w2t_base + i*64*128,
            buf, W, d, offset - 1);
        W -= d; buf ^= 1;
    }
    final_kernel<<<148,512,SM_FINAL>>>(alpha, w_out0, b_out0, w_out1, b_out1, (float*)d_out);
}